// round 6
// baseline (speedup 1.0000x reference)
#include <cuda_runtime.h>
#include <cuda_bf16.h>

// Scratch (device globals — no allocation allowed)
#define NMAX 20000
__device__ __align__(16) float g_ns_acc[NMAX * 64];    // h_ns_int (hs + scattered es)
__device__ __align__(16) float g_nv_acc[NMAX * 192];   // nv_int   (nv1 + scattered ev1)
__device__ __align__(16) float g_nt_norm[NMAX * 64];   // ||nt1||
__device__ __align__(16) float g_mid[NMAX * 96];       // silu(h_cat @ Wc1.T + bc1)

typedef unsigned long long u64;

__device__ __forceinline__ float sigm_(float x) { return 1.0f / (1.0f + __expf(-x)); }
__device__ __forceinline__ float silu_(float x) { return x * sigm_(x); }

__device__ __forceinline__ void red_add_v4(float* p, float4 v) {
    asm volatile("red.global.add.v4.f32 [%0], {%1,%2,%3,%4};"
                 :: "l"(p), "f"(v.x), "f"(v.y), "f"(v.z), "f"(v.w) : "memory");
}

// Packed fp32x2 FMA: a = x*w + a (elementwise on the two packed floats)
__device__ __forceinline__ void ffma2(u64& a, u64 x, u64 w) {
    asm("fma.rn.f32x2 %0, %1, %2, %0;" : "+l"(a) : "l"(x), "l"(w));
}
__device__ __forceinline__ float red2(u64 a) {
    return __uint_as_float((unsigned)a) + __uint_as_float((unsigned)(a >> 32));
}

// k-major weight layout in smem: row o at offset o*(K+1) + (o&1)  [floats]
// - (o&1) keeps every row offset EVEN => 8B-aligned 64-bit loads
// - stride K+1 odd => warp LDS.64 across rows {l} and {l+32} hits each
//   bank exactly twice (the 2-phase crossbar optimum)
__device__ __forceinline__ void load_wt_km(const float* __restrict__ W, float* sW,
                                           int O, int K) {
    for (int i = threadIdx.x; i < O * K; i += blockDim.x) {
        int o = i / K, k = i - o * K;
        sW[o * (K + 1) + (o & 1) + k] = W[i];
    }
}

template<int NO>
__device__ __forceinline__ void zeroU(u64 (&a)[8][NO]) {
#pragma unroll
    for (int r = 0; r < 8; r++)
#pragma unroll
        for (int o = 0; o < NO; o++) a[r][o] = 0ull;
}

// Warp micro-GEMM, packed-f32x2 accumulation.
// 8 rows; lane owns NOUT outputs at o = ocol + lane + 32*p.
// acc[r][p] holds packed (even-k, odd-k) partial sums; reduce with red2().
template<int K, int NOUT, bool XG>
__device__ __forceinline__ void wgemm8x2(const float* __restrict__ xbase, int xstride,
                                         const float* __restrict__ sW, int ocol,
                                         u64 (&acc)[8][NOUT], int lane) {
    int woff[NOUT];
#pragma unroll
    for (int p = 0; p < NOUT; p++) {
        int o = ocol + lane + 32 * p;
        woff[p] = o * (K + 1) + (o & 1);
    }
#pragma unroll 2
    for (int k = 0; k < K; k += 4) {
        u64 w[NOUT][2];
#pragma unroll
        for (int p = 0; p < NOUT; p++) {
            w[p][0] = *(const u64*)(sW + woff[p] + k);
            w[p][1] = *(const u64*)(sW + woff[p] + k + 2);
        }
#pragma unroll
        for (int r = 0; r < 8; r++) {
            ulonglong2 x;
            if (XG) x = __ldg((const ulonglong2*)(xbase + (size_t)r * xstride + k));
            else    x = *(const ulonglong2*)(xbase + (size_t)r * xstride + k);
#pragma unroll
            for (int p = 0; p < NOUT; p++) {
                ffma2(acc[r][p], x.x, w[p][0]);
                ffma2(acc[r][p], x.y, w[p][1]);
            }
        }
    }
}

// padded k-major weight region sizes (floats, 16B-aligned)
#define WKM(O, K) ((((O) * ((K) + 1) + 2) + 3) & ~3)

// ---------------------------------------------------------------------------
// Kernel A: hs -> g_ns_acc, nv1 -> g_nv_acc, ||nt1|| -> g_nt_norm
// smem: WKM(64,128) + 3*WKM(64,64) + 8*512 = 8260+12492+4096 = 24848 fl (99.4KB)
// ---------------------------------------------------------------------------
#define A_SMEM_BYTES ((WKM(64,128) + 3*WKM(64,64) + 8*512) * 4)

__global__ void __launch_bounds__(256, 2) nodeA_kernel(
    const float* __restrict__ h_ns, const float* __restrict__ h_nv,
    const float* __restrict__ h_nt,
    const float* __restrict__ Wns1, const float* __restrict__ bns1,
    const float* __restrict__ Wns2, const float* __restrict__ bns2,
    const float* __restrict__ Wnv1, const float* __restrict__ Wnt1, int N)
{
    extern __shared__ float sm[];
    float* sWns1 = sm;
    float* sWns2 = sWns1 + WKM(64,128);
    float* sWnv1 = sWns2 + WKM(64,64);
    float* sWnt1 = sWnv1 + WKM(64,64);
    float* sBuf  = sWnt1 + WKM(64,64);

    load_wt_km(Wns1, sWns1, 64, 128);
    load_wt_km(Wns2, sWns2, 64, 64);
    load_wt_km(Wnv1, sWnv1, 64, 64);
    load_wt_km(Wnt1, sWnt1, 64, 64);
    __syncthreads();

    const int lane = threadIdx.x & 31;
    const int warp = threadIdx.x >> 5;
    float* sT = sBuf + warp * 512;

    const float b1a = __ldg(bns1 + lane),      b1b = __ldg(bns1 + lane + 32);
    const float b2a = __ldg(bns2 + lane),      b2b = __ldg(bns2 + lane + 32);

    const int gw = blockIdx.x * 8 + warp;
    const int GW = gridDim.x * 8;
    const int ngroups = N >> 3;

    for (int g = gw; g < ngroups; g += GW) {
        const int n0 = g * 8;

        // hs layer 1 (K=128) -> silu -> sT
        u64 a1[8][2]; zeroU(a1);
        wgemm8x2<128, 2, true>(h_ns + (size_t)n0 * 128, 128, sWns1, 0, a1, lane);
        __syncwarp();
#pragma unroll
        for (int r = 0; r < 8; r++) {
            sT[r * 64 + lane]      = silu_(red2(a1[r][0]) + b1a);
            sT[r * 64 + lane + 32] = silu_(red2(a1[r][1]) + b1b);
        }
        __syncwarp();

        // hs layer 2 (K=64) -> g_ns_acc
        u64 a2[8][2]; zeroU(a2);
        wgemm8x2<64, 2, false>(sT, 64, sWns2, 0, a2, lane);
#pragma unroll
        for (int r = 0; r < 8; r++) {
            g_ns_acc[(size_t)(n0 + r) * 64 + lane]      = red2(a2[r][0]) + b2a;
            g_ns_acc[(size_t)(n0 + r) * 64 + lane + 32] = red2(a2[r][1]) + b2b;
        }

        // nv1 (3 components) -> g_nv_acc
#pragma unroll 1
        for (int a = 0; a < 3; a++) {
            u64 a3[8][2]; zeroU(a3);
            wgemm8x2<64, 2, true>(h_nv + (size_t)n0 * 192 + a * 64, 192, sWnv1, 0, a3, lane);
#pragma unroll
            for (int r = 0; r < 8; r++) {
                g_nv_acc[(size_t)(n0 + r) * 192 + a * 64 + lane]      = red2(a3[r][0]);
                g_nv_acc[(size_t)(n0 + r) * 192 + a * 64 + lane + 32] = red2(a3[r][1]);
            }
        }

        // ||nt1|| over the 9 (3x3) components
        float sq0[8], sq1[8];
#pragma unroll
        for (int r = 0; r < 8; r++) { sq0[r] = 0.0f; sq1[r] = 0.0f; }
#pragma unroll 1
        for (int c = 0; c < 9; c++) {
            u64 a4[8][2]; zeroU(a4);
            wgemm8x2<64, 2, true>(h_nt + (size_t)n0 * 576 + c * 64, 576, sWnt1, 0, a4, lane);
#pragma unroll
            for (int r = 0; r < 8; r++) {
                float t0 = red2(a4[r][0]), t1 = red2(a4[r][1]);
                sq0[r] += t0 * t0; sq1[r] += t1 * t1;
            }
        }
#pragma unroll
        for (int r = 0; r < 8; r++) {
            g_nt_norm[(size_t)(n0 + r) * 64 + lane]      = sqrtf(sq0[r]);
            g_nt_norm[(size_t)(n0 + r) * 64 + lane + 32] = sqrtf(sq1[r]);
        }
    }
}

// ---------------------------------------------------------------------------
// Edge kernel: es MLP + ev1, scatter-add into g_ns_acc / g_nv_acc
// smem: WKM(64,128) + 2*WKM(64,64) + 8*1024 = 8260+8328+8192 = 24780 fl (99.1KB)
// ---------------------------------------------------------------------------
#define E_SMEM_BYTES ((WKM(64,128) + 2*WKM(64,64) + 8*1024) * 4)

__global__ void __launch_bounds__(256, 2) edge_kernel(
    const float* __restrict__ h_es, const float* __restrict__ h_ev,
    const int* __restrict__ idx1, const int* __restrict__ idx2,
    const float* __restrict__ Wes1, const float* __restrict__ bes1,
    const float* __restrict__ Wes2, const float* __restrict__ bes2,
    const float* __restrict__ Wev1, int E)
{
    extern __shared__ float sm[];
    float* sWes1 = sm;
    float* sWes2 = sWes1 + WKM(64,128);
    float* sWev1 = sWes2 + WKM(64,64);
    float* sBuf  = sWev1 + WKM(64,64);

    load_wt_km(Wes1, sWes1, 64, 128);
    load_wt_km(Wes2, sWes2, 64, 64);
    load_wt_km(Wev1, sWev1, 64, 64);
    __syncthreads();

    const int lane = threadIdx.x & 31;
    const int warp = threadIdx.x >> 5;
    float* sT  = sBuf + warp * 1024;
    float* sEs = sT + 512;

    const float b1a = __ldg(bes1 + lane), b1b = __ldg(bes1 + lane + 32);
    const float b2a = __ldg(bes2 + lane), b2b = __ldg(bes2 + lane + 32);

    const int gw = blockIdx.x * 8 + warp;
    const int GW = gridDim.x * 8;
    const int ngroups = E >> 3;

    for (int g = gw; g < ngroups; g += GW) {
        const int e0 = g * 8;

        // GEMM1: t1 = silu(h_es @ Wes1.T + b) (K=128)
        u64 a1[8][2]; zeroU(a1);
        wgemm8x2<128, 2, true>(h_es + (size_t)e0 * 128, 128, sWes1, 0, a1, lane);
        __syncwarp();
#pragma unroll
        for (int r = 0; r < 8; r++) {
            sT[r * 64 + lane]      = silu_(red2(a1[r][0]) + b1a);
            sT[r * 64 + lane + 32] = silu_(red2(a1[r][1]) + b1b);
        }
        __syncwarp();

        // GEMM2: es = t1 @ Wes2.T + b (K=64) -> sEs
        u64 a2[8][2]; zeroU(a2);
        wgemm8x2<64, 2, false>(sT, 64, sWes2, 0, a2, lane);
#pragma unroll
        for (int r = 0; r < 8; r++) {
            sEs[r * 64 + lane]      = red2(a2[r][0]) + b2a;
            sEs[r * 64 + lane + 32] = red2(a2[r][1]) + b2b;
        }
        __syncwarp();

        // scatter es into g_ns_acc at idx1 and idx2 (v4 reds)
#pragma unroll
        for (int j = 0; j < 4; j++) {
            int cid = lane + 32 * j;
            int r = cid >> 4, c = (cid & 15) * 4;
            float4 v = *(const float4*)&sEs[r * 64 + c];
            int i1 = __ldg(idx1 + e0 + r), i2 = __ldg(idx2 + e0 + r);
            red_add_v4(g_ns_acc + (size_t)i1 * 64 + c, v);
            red_add_v4(g_ns_acc + (size_t)i2 * 64 + c, v);
        }

        // ev1 per component, scatter into g_nv_acc
#pragma unroll 1
        for (int a = 0; a < 3; a++) {
            u64 a3[8][2]; zeroU(a3);
            wgemm8x2<64, 2, true>(h_ev + (size_t)e0 * 192 + a * 64, 192, sWev1, 0, a3, lane);
            __syncwarp();
#pragma unroll
            for (int r = 0; r < 8; r++) {
                sEs[r * 64 + lane]      = red2(a3[r][0]);
                sEs[r * 64 + lane + 32] = red2(a3[r][1]);
            }
            __syncwarp();
#pragma unroll
            for (int j = 0; j < 4; j++) {
                int cid = lane + 32 * j;
                int r = cid >> 4, c = (cid & 15) * 4;
                float4 v = *(const float4*)&sEs[r * 64 + c];
                int i1 = __ldg(idx1 + e0 + r), i2 = __ldg(idx2 + e0 + r);
                red_add_v4(g_nv_acc + (size_t)i1 * 192 + a * 64 + c, v);
                red_add_v4(g_nv_acc + (size_t)i2 * 192 + a * 64 + c, v);
            }
        }
    }
}

// ---------------------------------------------------------------------------
// Kernel C1: h_cat = [ns_acc, ||nv_int||, nt_norm]; g_mid = silu(h_cat@Wc1.T+bc1)
// 512 threads (16 warps). smem: WKM(96,192) + 16*1536 = 18532+24576 fl (172KB)
// ---------------------------------------------------------------------------
#define C1_SMEM_BYTES ((WKM(96,192) + 16*1536) * 4)

__global__ void __launch_bounds__(512, 1) nodeC1_kernel(
    const float* __restrict__ Wc1, const float* __restrict__ bc1, int N)
{
    extern __shared__ float sm[];
    float* sWc1  = sm;
    float* sCatA = sWc1 + WKM(96,192);

    load_wt_km(Wc1, sWc1, 96, 192);
    __syncthreads();

    const int lane = threadIdx.x & 31;
    const int warp = threadIdx.x >> 5;
    float* cat = sCatA + warp * 1536;

    const float b0 = __ldg(bc1 + lane), b1 = __ldg(bc1 + lane + 32), b2 = __ldg(bc1 + lane + 64);

    const int gw = blockIdx.x * 16 + warp;
    const int GW = gridDim.x * 16;
    const int ngroups = N >> 3;

    for (int g = gw; g < ngroups; g += GW) {
        const int n0 = g * 8;
        __syncwarp();
#pragma unroll
        for (int r = 0; r < 8; r++) {
            const size_t n = (size_t)(n0 + r);
            float2 s = *(const float2*)&g_ns_acc[n * 64 + 2 * lane];
            *(float2*)&cat[r * 192 + 2 * lane] = s;
            float2 v0 = *(const float2*)&g_nv_acc[n * 192 + 0   + 2 * lane];
            float2 v1 = *(const float2*)&g_nv_acc[n * 192 + 64  + 2 * lane];
            float2 v2 = *(const float2*)&g_nv_acc[n * 192 + 128 + 2 * lane];
            float2 nn;
            nn.x = sqrtf(v0.x * v0.x + v1.x * v1.x + v2.x * v2.x);
            nn.y = sqrtf(v0.y * v0.y + v1.y * v1.y + v2.y * v2.y);
            *(float2*)&cat[r * 192 + 64 + 2 * lane] = nn;
            float2 tn = *(const float2*)&g_nt_norm[n * 64 + 2 * lane];
            *(float2*)&cat[r * 192 + 128 + 2 * lane] = tn;
        }
        __syncwarp();

        u64 acc[8][3]; zeroU(acc);
        wgemm8x2<192, 3, false>(cat, 192, sWc1, 0, acc, lane);
#pragma unroll
        for (int r = 0; r < 8; r++) {
            const size_t n = (size_t)(n0 + r);
            g_mid[n * 96 + lane]      = silu_(red2(acc[r][0]) + b0);
            g_mid[n * 96 + lane + 32] = silu_(red2(acc[r][1]) + b1);
            g_mid[n * 96 + lane + 64] = silu_(red2(acc[r][2]) + b2);
        }
    }
}

// ---------------------------------------------------------------------------
// Kernel C2: out = mid@Wc2.T+bc2; fused ns/nv/nt outputs with sigmoid gates
// 512 threads (16 warps). smem: WKM(256,96)+2*WKM(64,64)+16*1024
//   = 24836+8328+16384 = 49548 fl (198.2KB)
// ---------------------------------------------------------------------------
#define C2_SMEM_BYTES ((WKM(256,96) + 2*WKM(64,64) + 16*1024) * 4)

__global__ void __launch_bounds__(512, 1) nodeC2_kernel(
    const float* __restrict__ h_ns, const float* __restrict__ h_nv,
    const float* __restrict__ h_nt,
    const float* __restrict__ Wnv2, const float* __restrict__ Wnt2,
    const float* __restrict__ Wc2, const float* __restrict__ bc2,
    float* __restrict__ out, int N)
{
    extern __shared__ float sm[];
    float* sWc2  = sm;
    float* sWnv2 = sWc2 + WKM(256,96);
    float* sWnt2 = sWnv2 + WKM(64,64);
    float* sGateA = sWnt2 + WKM(64,64);

    load_wt_km(Wc2, sWc2, 256, 96);
    load_wt_km(Wnv2, sWnv2, 64, 64);
    load_wt_km(Wnt2, sWnt2, 64, 64);
    __syncthreads();

    const int lane = threadIdx.x & 31;
    const int warp = threadIdx.x >> 5;
    float* gate = sGateA + warp * 1024;

    float* ns_out = out;
    float* nv_out = out + (size_t)N * 128;
    float* nt_out = out + (size_t)N * 320;

    float bA[4], bB[4];
#pragma unroll
    for (int p = 0; p < 4; p++) {
        bA[p] = __ldg(bc2 + lane + 32 * p);
        bB[p] = __ldg(bc2 + 128 + lane + 32 * p);
    }

    const int gw = blockIdx.x * 16 + warp;
    const int GW = gridDim.x * 16;
    const int ngroups = N >> 3;

    for (int g = gw; g < ngroups; g += GW) {
        const int n0 = g * 8;

        // out cols 0..127 -> ns_out (+ h_ns residual)
        u64 accA[8][4]; zeroU(accA);
        wgemm8x2<96, 4, true>(g_mid + (size_t)n0 * 96, 96, sWc2, 0, accA, lane);
#pragma unroll
        for (int r = 0; r < 8; r++) {
            const size_t n = (size_t)(n0 + r);
#pragma unroll
            for (int p = 0; p < 4; p++) {
                float h = __ldg(h_ns + n * 128 + lane + 32 * p);
                ns_out[n * 128 + lane + 32 * p] = red2(accA[r][p]) + bA[p] + h;
            }
        }

        // out cols 128..255 -> gates
        u64 accB[8][4]; zeroU(accB);
        wgemm8x2<96, 4, true>(g_mid + (size_t)n0 * 96, 96, sWc2, 128, accB, lane);
        __syncwarp();
#pragma unroll
        for (int r = 0; r < 8; r++)
#pragma unroll
            for (int p = 0; p < 4; p++)
                gate[r * 128 + lane + 32 * p] = sigm_(red2(accB[r][p]) + bB[p]);
        __syncwarp();

        // nv_out = gate_nv * (h_nv @ Wnv2.T) + h_nv
#pragma unroll 1
        for (int a = 0; a < 3; a++) {
            u64 acc[8][2]; zeroU(acc);
            wgemm8x2<64, 2, true>(h_nv + (size_t)n0 * 192 + a * 64, 192, sWnv2, 0, acc, lane);
#pragma unroll
            for (int r = 0; r < 8; r++) {
                const size_t n = (size_t)(n0 + r);
                float h0 = __ldg(h_nv + n * 192 + a * 64 + lane);
                float h1 = __ldg(h_nv + n * 192 + a * 64 + lane + 32);
                nv_out[n * 192 + a * 64 + lane]      = gate[r * 128 + lane]      * red2(acc[r][0]) + h0;
                nv_out[n * 192 + a * 64 + lane + 32] = gate[r * 128 + lane + 32] * red2(acc[r][1]) + h1;
            }
        }

        // nt_out = gate_nt * (h_nt @ Wnt2.T) + h_nt
#pragma unroll 1
        for (int c = 0; c < 9; c++) {
            u64 acc[8][2]; zeroU(acc);
            wgemm8x2<64, 2, true>(h_nt + (size_t)n0 * 576 + c * 64, 576, sWnt2, 0, acc, lane);
#pragma unroll
            for (int r = 0; r < 8; r++) {
                const size_t n = (size_t)(n0 + r);
                float h0 = __ldg(h_nt + n * 576 + c * 64 + lane);
                float h1 = __ldg(h_nt + n * 576 + c * 64 + lane + 32);
                nt_out[n * 576 + c * 64 + lane]      = gate[r * 128 + 64 + lane] * red2(acc[r][0]) + h0;
                nt_out[n * 576 + c * 64 + lane + 32] = gate[r * 128 + 96 + lane] * red2(acc[r][1]) + h1;
            }
        }
    }
}

// ---------------------------------------------------------------------------
extern "C" void kernel_launch(void* const* d_in, const int* in_sizes, int n_in,
                              void* d_out, int out_size)
{
    const float* h_ns = (const float*)d_in[0];
    const float* h_nv = (const float*)d_in[1];
    const float* h_nt = (const float*)d_in[2];
    const float* h_es = (const float*)d_in[3];
    const float* h_ev = (const float*)d_in[4];
    const int*   idx1 = (const int*)d_in[5];
    const int*   idx2 = (const int*)d_in[6];
    const float* Wns1 = (const float*)d_in[7];
    const float* bns1 = (const float*)d_in[8];
    const float* Wns2 = (const float*)d_in[9];
    const float* bns2 = (const float*)d_in[10];
    const float* Wes1 = (const float*)d_in[11];
    const float* bes1 = (const float*)d_in[12];
    const float* Wes2 = (const float*)d_in[13];
    const float* bes2 = (const float*)d_in[14];
    const float* Wnv1 = (const float*)d_in[15];
    const float* Wnv2 = (const float*)d_in[16];
    const float* Wev1 = (const float*)d_in[17];
    const float* Wnt1 = (const float*)d_in[18];
    const float* Wnt2 = (const float*)d_in[19];
    const float* Wc1  = (const float*)d_in[20];
    const float* bc1  = (const float*)d_in[21];
    const float* Wc2  = (const float*)d_in[22];
    const float* bc2  = (const float*)d_in[23];
    float* out = (float*)d_out;

    const int N = in_sizes[0] / 128;   // h_ns is (N, 128)
    const int E = in_sizes[5];         // atom_index1 is (E,)

    cudaFuncSetAttribute(nodeA_kernel,  cudaFuncAttributeMaxDynamicSharedMemorySize, A_SMEM_BYTES);
    cudaFuncSetAttribute(edge_kernel,   cudaFuncAttributeMaxDynamicSharedMemorySize, E_SMEM_BYTES);
    cudaFuncSetAttribute(nodeC1_kernel, cudaFuncAttributeMaxDynamicSharedMemorySize, C1_SMEM_BYTES);
    cudaFuncSetAttribute(nodeC2_kernel, cudaFuncAttributeMaxDynamicSharedMemorySize, C2_SMEM_BYTES);

    nodeA_kernel<<<304, 256, A_SMEM_BYTES>>>(
        h_ns, h_nv, h_nt, Wns1, bns1, Wns2, bns2, Wnv1, Wnt1, N);

    edge_kernel<<<304, 256, E_SMEM_BYTES>>>(
        h_es, h_ev, idx1, idx2, Wes1, bes1, Wes2, bes2, Wev1, E);

    nodeC1_kernel<<<152, 512, C1_SMEM_BYTES>>>(Wc1, bc1, N);

    nodeC2_kernel<<<152, 512, C2_SMEM_BYTES>>>(
        h_ns, h_nv, h_nt, Wnv2, Wnt2, Wc2, bc2, out, N);
}